// round 2
// baseline (speedup 1.0000x reference)
#include <cuda_runtime.h>

#define BB 2
#define CC 32
#define DD 64
#define HH 128
#define WW 128
#define NBC (BB*CC)
#define NSLICE (BB*CC*DD)

// Per-slice partials: [ssum, sx, sy, sz]. Fully written every run -> no init needed.
__device__ float4 g_part[NSLICE];

// ---- packed f32x2 helpers ----
__device__ __forceinline__ void unpack2(unsigned long long v, float& lo, float& hi) {
    asm("mov.b64 {%0,%1}, %2;" : "=f"(lo), "=f"(hi) : "l"(v));
}

// acc += v (packed add)
__device__ __forceinline__ void acc2(unsigned long long& acc, unsigned long long v) {
    asm("add.rn.f32x2 %0, %0, %1;" : "+l"(acc) : "l"(v));
}

// acc += |b - a| elementwise on packed f32x2
__device__ __forceinline__ void absdiff_acc2(unsigned long long& acc,
                                             unsigned long long a,
                                             unsigned long long b,
                                             unsigned long long neg1) {
    unsigned long long d;
    asm("fma.rn.f32x2 %0, %1, %2, %3;" : "=l"(d) : "l"(a), "l"(neg1), "l"(b)); // d = b - a
    asm("and.b64 %0, %0, 0x7FFFFFFF7FFFFFFF;" : "+l"(d));                      // |d|
    asm("add.rn.f32x2 %0, %0, %1;" : "+l"(acc) : "l"(d));
}

__device__ __forceinline__ ulonglong2 ldrow(const float* base, int h, int lane) {
    return reinterpret_cast<const ulonglong2*>(base + h * WW)[lane];
}

// One CTA per z-slice. 8 warps; warp w walks rows [16w, 16w+16) sequentially,
// carrying the row in registers so the y-diff needs no second load.
__global__ __launch_bounds__(256) void slice_kernel(const float* __restrict__ seg) {
    const int s = blockIdx.x;
    const int d = s & (DD - 1);

    const float* slice  = seg + (size_t)s * (HH * WW);
    const float* nslice = slice + (HH * WW);          // read only if d < DD-1

    const int warp = threadIdx.x >> 5;
    const int lane = threadIdx.x & 31;
    const bool has_z = (d < DD - 1);

    const unsigned long long neg1 = 0xBF800000BF800000ULL;  // (-1.f, -1.f)

    unsigned long long acc_s = 0ULL, acc_y = 0ULL, acc_z = 0ULL;
    float sx = 0.f;

    const int h0 = warp * 16;
    ulonglong2 row = ldrow(slice, h0, lane);

    #pragma unroll 4
    for (int i = 0; i < 16; i++) {
        const int h = h0 + i;
        const bool hasn = (h < HH - 1);

        ulonglong2 nxt;
        if (hasn) nxt = ldrow(slice, h + 1, lane);

        // slice sum (packed)
        acc2(acc_s, row.x);
        acc2(acc_s, row.y);

        // x-diffs: scalar within float4 + one cross-lane shuffle
        float x0, x1, x2, x3;
        unpack2(row.x, x0, x1);
        unpack2(row.y, x2, x3);
        const float nlx = __shfl_down_sync(0xffffffffu, x0, 1);
        sx += fabsf(x1 - x0) + fabsf(x2 - x1) + fabsf(x3 - x2);
        if (lane < 31) sx += fabsf(nlx - x3);

        // z-diff vs same position in next slice (L2-resident: adjacent CTA's cur)
        if (has_z) {
            const ulonglong2 zn = ldrow(nslice, h, lane);
            absdiff_acc2(acc_z, row.x, zn.x, neg1);
            absdiff_acc2(acc_z, row.y, zn.y, neg1);
        }

        // y-diff vs carried next row
        if (hasn) {
            absdiff_acc2(acc_y, row.x, nxt.x, neg1);
            absdiff_acc2(acc_y, row.y, nxt.y, neg1);
            row = nxt;
        }
    }

    float a, b;
    unpack2(acc_s, a, b); float ssum = a + b;
    unpack2(acc_y, a, b); float sy   = a + b;
    unpack2(acc_z, a, b); float sz   = a + b;

    // warp reduce
    #pragma unroll
    for (int off = 16; off > 0; off >>= 1) {
        ssum += __shfl_xor_sync(0xffffffffu, ssum, off);
        sx   += __shfl_xor_sync(0xffffffffu, sx,   off);
        sy   += __shfl_xor_sync(0xffffffffu, sy,   off);
        sz   += __shfl_xor_sync(0xffffffffu, sz,   off);
    }

    __shared__ float sh[4][8];
    if (lane == 0) { sh[0][warp] = ssum; sh[1][warp] = sx; sh[2][warp] = sy; sh[3][warp] = sz; }
    __syncthreads();

    if (threadIdx.x == 0) {
        float t0 = 0.f, t1 = 0.f, t2 = 0.f, t3 = 0.f;
        #pragma unroll
        for (int w = 0; w < 8; w++) {
            t0 += sh[0][w]; t1 += sh[1][w]; t2 += sh[2][w]; t3 += sh[3][w];
        }
        g_part[s] = make_float4(t0, t1, t2, t3);
    }
}

// 64 threads: thread i owns (b,c)=i, reduces its 64 slices, then cross-thread reduce.
__global__ void finalize_kernel(float* __restrict__ out) {
    const int i = threadIdx.x;   // 0..63

    double crown = 0.0, root = 0.0, tx = 0.0, ty = 0.0, tz = 0.0;
    for (int dd = 0; dd < DD; dd++) {
        const float4 v = g_part[i * DD + dd];
        if (dd < DD / 2) crown += (double)v.x; else root += (double)v.x;
        tx += (double)v.y; ty += (double)v.z; tz += (double)v.w;
    }

    double loss = 0.0;
    if ((crown + root) > 0.0 && root > 0.0) {
        const double r = crown / root - 1.2;
        loss = r * r;
    }

    // reduce loss/tx/ty/tz across 64 threads (2 warps)
    #pragma unroll
    for (int off = 16; off > 0; off >>= 1) {
        loss += __shfl_xor_sync(0xffffffffu, loss, off);
        tx   += __shfl_xor_sync(0xffffffffu, tx,   off);
        ty   += __shfl_xor_sync(0xffffffffu, ty,   off);
        tz   += __shfl_xor_sync(0xffffffffu, tz,   off);
    }

    __shared__ double sh[4][2];
    const int warp = i >> 5;
    if ((i & 31) == 0) { sh[0][warp] = loss; sh[1][warp] = tx; sh[2][warp] = ty; sh[3][warp] = tz; }
    __syncthreads();

    if (i == 0) {
        const double L  = sh[0][0] + sh[0][1];
        const double Tx = sh[1][0] + sh[1][1];
        const double Ty = sh[2][0] + sh[2][1];
        const double Tz = sh[3][0] + sh[3][1];

        const double cr_loss = L / (double)NBC;
        const double Nx = (double)BB * CC * DD * HH * (WW - 1);
        const double Ny = (double)BB * CC * DD * (HH - 1) * WW;
        const double Nz = (double)BB * CC * (DD - 1) * HH * WW;
        const double tv = Tx / Nx + Ty / Ny + Tz / Nz;

        const double crown_root = cr_loss * 2.0;   // CROWN_ROOT_W
        const double smooth     = tv * 1.5;        // SMOOTH_W
        out[0] = (float)crown_root;
        out[1] = (float)smooth;
        out[2] = (float)(crown_root + smooth);
    }
}

extern "C" void kernel_launch(void* const* d_in, const int* in_sizes, int n_in,
                              void* d_out, int out_size) {
    const float* seg = (const float*)d_in[0];
    float* out = (float*)d_out;

    slice_kernel<<<NSLICE, 256>>>(seg);
    finalize_kernel<<<1, NBC>>>(out);
}